// round 11
// baseline (speedup 1.0000x reference)
#include <cuda_runtime.h>
#include <math.h>

#define BB 8
#define SS 128
#define DD 256
#define HH 8
#define TT 129
#define HDIM 32

typedef unsigned long long ull;

// Scratch (no allocations allowed)
__device__ __align__(16) float g_A [BB*SS*DD];   // desc @ We1[:256] + be1
__device__ __align__(16) float g_Bm[BB*SS*DD];   // desc @ We1[256:]
__device__ __align__(16) float g_V [BB*TT*DD];   // nv @ Wv + bv
__device__ __align__(16) float g_u [DD*HH];      // We2 folded with wa_e
__device__ __align__(16) float g_wq[DD*HH];
__device__ __align__(16) float g_wk[DD*HH];
__device__ float g_qa[BB*HH*TT];                 // includes bq_eff + ba + be2_eff
__device__ float g_ka[BB*HH*TT];                 // includes bk_eff
__device__ float g_beff[3*HH];
__device__ float g_sA[BB*SS];
__device__ float g_qA[BB*SS];
__device__ float g_sB[BB*SS];
__device__ float g_qB[BB*SS];
__device__ __align__(16) float g_G [BB*SS*SS];   // Gram: dot(A'_i, Bm_j)
__device__ __align__(16) ull g_BmT[BB*128*128];  // [b][d2][j]
__device__ __align__(16) ull g_AT [BB*128*128];  // same for A'
__device__ __align__(16) ull g_u2 [128*8];       // [d2][h]
__device__ __align__(16) ull g_lnp[128*2];       // [d2]{gamma2, beta2}
__device__ float g_E[BB*HH*129*128];             // raw head scores

// ---- f32x2 helpers -------------------------------------------------------
__device__ __forceinline__ ull pk(float a, float b) {
    ull r; asm("mov.b64 %0,{%1,%2};" : "=l"(r) : "f"(a), "f"(b)); return r;
}
__device__ __forceinline__ void upk(ull v, float& a, float& b) {
    asm("mov.b64 {%0,%1},%2;" : "=f"(a), "=f"(b) : "l"(v));
}
__device__ __forceinline__ ull add2(ull a, ull b) {
    ull r; asm("add.rn.f32x2 %0,%1,%2;" : "=l"(r) : "l"(a), "l"(b)); return r;
}
__device__ __forceinline__ ull mul2(ull a, ull b) {
    ull r; asm("mul.rn.f32x2 %0,%1,%2;" : "=l"(r) : "l"(a), "l"(b)); return r;
}
__device__ __forceinline__ ull fma2(ull a, ull b, ull c) {
    ull r; asm("fma.rn.f32x2 %0,%1,%2,%3;" : "=l"(r) : "l"(a), "l"(b), "l"(c)); return r;
}
__device__ __forceinline__ ull relu2(ull v) {
    ull a; asm("and.b64 %0,%1,0x7FFFFFFF7FFFFFFF;" : "=l"(a) : "l"(v));
    const ull HALF2 = 0x3F0000003F000000ULL;
    return mul2(add2(v, a), HALF2);
}

// ---------------------------------------------------------------------------
__global__ void __launch_bounds__(256) k_setup(
        const float* __restrict__ Wq, const float* __restrict__ Wk,
        const float* __restrict__ We2, const float* __restrict__ wa,
        const float* __restrict__ bq, const float* __restrict__ bk,
        const float* __restrict__ be2) {
    int blk = blockIdx.x;
    if (blk < 24) {
        int which = blk >> 3, h = blk & 7;
        const float* W = (which == 0) ? Wq : (which == 1) ? Wk : We2;
        float* dst = (which == 0) ? g_wq : (which == 1) ? g_wk : g_u;
        __shared__ float was[32];
        if (threadIdx.x < 32) was[threadIdx.x] = wa[which * 32 + threadIdx.x];
        __syncthreads();
        int d = threadIdx.x;
        const float4* wp = (const float4*)(W + d * 256 + h * 32);
        float s = 0.f;
        #pragma unroll
        for (int e4 = 0; e4 < 8; e4++) {
            float4 v = wp[e4];
            s = fmaf(v.x, was[e4*4+0], s);
            s = fmaf(v.y, was[e4*4+1], s);
            s = fmaf(v.z, was[e4*4+2], s);
            s = fmaf(v.w, was[e4*4+3], s);
        }
        dst[d * 8 + h] = s;
    } else {
        __shared__ float was[96];
        if (threadIdx.x < 96) was[threadIdx.x] = wa[threadIdx.x];
        __syncthreads();
        int d = threadIdx.x;
        if (d < 24) {
            int h = d & 7, which = d >> 3;
            const float* bp = (which == 0) ? bq : (which == 1) ? bk : be2;
            int wo = which * 32;
            float s = 0.f;
            for (int e = 0; e < 32; e++) s += bp[h * 32 + e] * was[wo + e];
            g_beff[d] = s;
        }
    }
}

// ---------------------------------------------------------------------------
__device__ __forceinline__ void gemm_tile64(const float* __restrict__ X,
                                            const float* __restrict__ W,
                                            const float* __restrict__ bias,
                                            int M, int wRowOff, int bm, int bn,
                                            float* __restrict__ C,
                                            float* XsT, float* Ws) {
    int tid = threadIdx.x;
    int xr = tid >> 2, xc = (tid & 3) * 4;
    int wk = tid >> 4, wn = (tid & 15) * 4;
    int tr = (tid >> 4) * 4, tc = (tid & 15) * 4;
    float acc[4][4];
    #pragma unroll
    for (int r = 0; r < 4; r++)
        #pragma unroll
        for (int c = 0; c < 4; c++) acc[r][c] = 0.f;

    int gr = bm + xr;
    float4 xv, wv;
    if (gr < M) xv = *(const float4*)&X[gr * 256 + xc];
    else xv = make_float4(0.f, 0.f, 0.f, 0.f);
    wv = *(const float4*)&W[(wRowOff + wk) * 256 + bn + wn];

    #pragma unroll 1
    for (int p = 0; p < 16; p++) {
        XsT[(xc + 0) * 68 + xr] = xv.x;
        XsT[(xc + 1) * 68 + xr] = xv.y;
        XsT[(xc + 2) * 68 + xr] = xv.z;
        XsT[(xc + 3) * 68 + xr] = xv.w;
        *(float4*)&Ws[wk * 68 + wn] = wv;
        __syncthreads();
        if (p < 15) {
            int k0 = (p + 1) * 16;
            if (gr < M) xv = *(const float4*)&X[gr * 256 + k0 + xc];
            wv = *(const float4*)&W[(wRowOff + k0 + wk) * 256 + bn + wn];
        }
        #pragma unroll
        for (int kk = 0; kk < 16; kk++) {
            float4 a = *(const float4*)&XsT[kk * 68 + tr];
            float4 b = *(const float4*)&Ws[kk * 68 + tc];
            acc[0][0] = fmaf(a.x, b.x, acc[0][0]); acc[0][1] = fmaf(a.x, b.y, acc[0][1]);
            acc[0][2] = fmaf(a.x, b.z, acc[0][2]); acc[0][3] = fmaf(a.x, b.w, acc[0][3]);
            acc[1][0] = fmaf(a.y, b.x, acc[1][0]); acc[1][1] = fmaf(a.y, b.y, acc[1][1]);
            acc[1][2] = fmaf(a.y, b.z, acc[1][2]); acc[1][3] = fmaf(a.y, b.w, acc[1][3]);
            acc[2][0] = fmaf(a.z, b.x, acc[2][0]); acc[2][1] = fmaf(a.z, b.y, acc[2][1]);
            acc[2][2] = fmaf(a.z, b.z, acc[2][2]); acc[2][3] = fmaf(a.z, b.w, acc[2][3]);
            acc[3][0] = fmaf(a.w, b.x, acc[3][0]); acc[3][1] = fmaf(a.w, b.y, acc[3][1]);
            acc[3][2] = fmaf(a.w, b.z, acc[3][2]); acc[3][3] = fmaf(a.w, b.w, acc[3][3]);
        }
        __syncthreads();
    }
    #pragma unroll
    for (int r = 0; r < 4; r++) {
        int gr2 = bm + tr + r;
        if (gr2 < M) {
            float4 v = make_float4(acc[r][0], acc[r][1], acc[r][2], acc[r][3]);
            if (bias) {
                v.x += bias[bn + tc + 0]; v.y += bias[bn + tc + 1];
                v.z += bias[bn + tc + 2]; v.w += bias[bn + tc + 3];
            }
            *(float4*)&C[gr2 * 256 + bn + tc] = v;
        }
    }
}

__global__ void __launch_bounds__(256) k_fused(const float* __restrict__ desc,
                                               const float* __restrict__ nv,
                                               const float* __restrict__ We1,
                                               const float* __restrict__ be1,
                                               const float* __restrict__ Wv,
                                               const float* __restrict__ bv,
                                               const float* __restrict__ ba) {
    __shared__ __align__(16) float XsT[16 * 68];
    __shared__ __align__(16) float Ws[16 * 68];
    int t = blockIdx.x;
    int tid = threadIdx.x;
    if (t < 128) {
        int mt = t & 15, nt = t >> 4;
        bool isB = nt >= 4;
        gemm_tile64(desc, We1, isB ? (const float*)0 : be1, BB * SS,
                    isB ? 256 : 0, mt * 64, (nt & 3) * 64,
                    isB ? g_Bm : g_A, XsT, Ws);
    } else if (t < 196) {
        int t2 = t - 128;
        int mt = t2 % 17, nt = t2 / 17;
        gemm_tile64(nv, Wv, bv, BB * TT, 0, mt * 64, nt * 64, g_V, XsT, Ws);
    } else {
        int w = tid >> 5, lane = tid & 31;
        int row = (t - 196) * 8 + w;
        int b = row / TT, tt = row % TT;
        float accq[8], acck[8];
        #pragma unroll
        for (int h = 0; h < 8; h++) { accq[h] = 0.f; acck[h] = 0.f; }
        #pragma unroll
        for (int k = 0; k < 8; k++) {
            int d = lane + 32 * k;
            float xv = nv[row * DD + d];
            #pragma unroll
            for (int h = 0; h < 8; h++) {
                accq[h] = fmaf(xv, g_wq[d * 8 + h], accq[h]);
                acck[h] = fmaf(xv, g_wk[d * 8 + h], acck[h]);
            }
        }
        #pragma unroll
        for (int h = 0; h < 8; h++) {
            #pragma unroll
            for (int off = 16; off; off >>= 1) {
                accq[h] += __shfl_xor_sync(0xffffffffu, accq[h], off);
                acck[h] += __shfl_xor_sync(0xffffffffu, acck[h], off);
            }
        }
        if (lane == 0) {
            float bav = ba[0];
            #pragma unroll
            for (int h = 0; h < 8; h++) {
                g_qa[(b * HH + h) * TT + tt] = accq[h] + g_beff[h] + bav + g_beff[16 + h];
                g_ka[(b * HH + h) * TT + tt] = acck[h] + g_beff[8 + h];
            }
        }
    }
}

// ---------------------------------------------------------------------------
// k_stats: 0..31 Gram, 32..63 row stats, 64..319 transposes, 320 const packing
__global__ void __launch_bounds__(256) k_stats(const float* __restrict__ lng,
                                               const float* __restrict__ lnb) {
    int t = blockIdx.x, tid = threadIdx.x;
    if (t < 32) {
        __shared__ __align__(16) float As[16 * 68];
        __shared__ __align__(16) float Bs[16 * 68];
        int b = t >> 2, q = t & 3;
        int ti = (q >> 1) * 64, tj = (q & 1) * 64;
        int xr = tid >> 2, xc = (tid & 3) * 4;
        int tr = (tid >> 4) * 4, tc = (tid & 15) * 4;
        float acc[4][4];
        #pragma unroll
        for (int r = 0; r < 4; r++)
            #pragma unroll
            for (int c = 0; c < 4; c++) acc[r][c] = 0.f;

        const float* Abase = g_A + (b * 128 + ti) * 256;
        const float* Bbase = g_Bm + (b * 128 + tj) * 256;
        float4 av = *(const float4*)&Abase[xr * 256 + xc];
        float4 bv = *(const float4*)&Bbase[xr * 256 + xc];
        #pragma unroll 1
        for (int p = 0; p < 16; p++) {
            As[(xc + 0) * 68 + xr] = av.x; As[(xc + 1) * 68 + xr] = av.y;
            As[(xc + 2) * 68 + xr] = av.z; As[(xc + 3) * 68 + xr] = av.w;
            Bs[(xc + 0) * 68 + xr] = bv.x; Bs[(xc + 1) * 68 + xr] = bv.y;
            Bs[(xc + 2) * 68 + xr] = bv.z; Bs[(xc + 3) * 68 + xr] = bv.w;
            __syncthreads();
            if (p < 15) {
                int k0 = (p + 1) * 16;
                av = *(const float4*)&Abase[xr * 256 + k0 + xc];
                bv = *(const float4*)&Bbase[xr * 256 + k0 + xc];
            }
            #pragma unroll
            for (int kk = 0; kk < 16; kk++) {
                float4 a = *(const float4*)&As[kk * 68 + tr];
                float4 b2 = *(const float4*)&Bs[kk * 68 + tc];
                acc[0][0] = fmaf(a.x, b2.x, acc[0][0]); acc[0][1] = fmaf(a.x, b2.y, acc[0][1]);
                acc[0][2] = fmaf(a.x, b2.z, acc[0][2]); acc[0][3] = fmaf(a.x, b2.w, acc[0][3]);
                acc[1][0] = fmaf(a.y, b2.x, acc[1][0]); acc[1][1] = fmaf(a.y, b2.y, acc[1][1]);
                acc[1][2] = fmaf(a.y, b2.z, acc[1][2]); acc[1][3] = fmaf(a.y, b2.w, acc[1][3]);
                acc[2][0] = fmaf(a.z, b2.x, acc[2][0]); acc[2][1] = fmaf(a.z, b2.y, acc[2][1]);
                acc[2][2] = fmaf(a.z, b2.z, acc[2][2]); acc[2][3] = fmaf(a.z, b2.w, acc[2][3]);
                acc[3][0] = fmaf(a.w, b2.x, acc[3][0]); acc[3][1] = fmaf(a.w, b2.y, acc[3][1]);
                acc[3][2] = fmaf(a.w, b2.z, acc[3][2]); acc[3][3] = fmaf(a.w, b2.w, acc[3][3]);
            }
            __syncthreads();
        }
        #pragma unroll
        for (int r = 0; r < 4; r++) {
            float4 v = make_float4(acc[r][0], acc[r][1], acc[r][2], acc[r][3]);
            *(float4*)&g_G[(b * 128 + ti + tr + r) * 128 + tj + tc] = v;
        }
    } else if (t < 64) {
        int w = tid >> 5, lane = tid & 31;
        int r0 = (t - 32) * 64;
        for (int it = 0; it < 8; it++) {
            int row = r0 + w * 8 + it;
            const float* src = (row < 1024) ? (g_A + row * 256) : (g_Bm + (row - 1024) * 256);
            const float4* sp = (const float4*)(src + lane * 8);
            float4 v0 = sp[0], v1 = sp[1];
            float s = v0.x + v0.y + v0.z + v0.w + v1.x + v1.y + v1.z + v1.w;
            float q = v0.x*v0.x + v0.y*v0.y + v0.z*v0.z + v0.w*v0.w
                    + v1.x*v1.x + v1.y*v1.y + v1.z*v1.z + v1.w*v1.w;
            #pragma unroll
            for (int off = 16; off; off >>= 1) {
                s += __shfl_xor_sync(0xffffffffu, s, off);
                q += __shfl_xor_sync(0xffffffffu, q, off);
            }
            if (lane == 0) {
                if (row < 1024) { g_sA[row] = s; g_qA[row] = q; }
                else            { g_sB[row - 1024] = s; g_qB[row - 1024] = q; }
            }
        }
    } else if (t < 320) {
        __shared__ ull ts[32][33];
        int tb = t - 64;
        int b = tb >> 5, m = (tb >> 4) & 1, tile = tb & 15;
        int td = tile >> 2, tj = tile & 3;
        const float* src = m ? g_Bm : g_A;
        ull* dst = m ? g_BmT : g_AT;
        int ty = tid >> 5, tx = tid & 31;
        #pragma unroll
        for (int r = 0; r < 4; r++) {
            int jloc = ty + 8 * r;
            int j = tj * 32 + jloc;
            int d2 = td * 32 + tx;
            float2 v = *(const float2*)&src[(b * 128 + j) * 256 + 2 * d2];
            ts[jloc][tx] = pk(v.x, v.y);
        }
        __syncthreads();
        #pragma unroll
        for (int r = 0; r < 4; r++) {
            int d2loc = ty + 8 * r;
            int d2 = td * 32 + d2loc;
            int j = tj * 32 + tx;
            dst[b * 16384 + d2 * 128 + j] = ts[tx][d2loc];
        }
    } else {
        for (int idx = tid; idx < 1024; idx += 256) {
            int d2 = idx >> 3, h = idx & 7;
            g_u2[idx] = pk(g_u[(2 * d2) * 8 + h], g_u[(2 * d2 + 1) * 8 + h]);
        }
        if (tid < 128) {
            g_lnp[2 * tid]     = pk(lng[2 * tid], lng[2 * tid + 1]);
            g_lnp[2 * tid + 1] = pk(lnb[2 * tid], lnb[2 * tid + 1]);
        }
    }
}

// ---------------------------------------------------------------------------
// k_edge v4: 256 threads, thread = (s = tid>>7, jm1 = tid&127). One pair/thread.
__global__ void __launch_bounds__(256) k_edge() {
    int blk = blockIdx.x;
    int b = blk / 65, ib = blk % 65;
    int i0 = ib * 2;
    int tid = threadIdx.x;
    int s = tid >> 7;
    int jm1 = tid & 127;
    int i = i0 + s;

    __shared__ __align__(16) ull sU[1024];   // [d2][h]
    __shared__ __align__(16) ull sL[256];    // [d2]{g,b}
    __shared__ __align__(16) ull sA2[256];   // rows i0-1, i0 packed by d2

    for (int idx = tid; idx < 1024; idx += 256) sU[idx] = g_u2[idx];
    sL[tid] = g_lnp[tid];
    {
        int r = tid >> 7;
        int d2i = tid & 127;
        int row = i0 + r - 1;
        if (row >= 0 && row < 128)
            sA2[r * 128 + d2i] = ((const ull*)(g_A + (b * 128 + row) * 256))[d2i];
    }
    __syncthreads();

    if (i > 128) return;

    const float invD = 1.f / 256.f;
    float sBj = g_sB[b * 128 + jm1], qBj = g_qB[b * 128 + jm1];
    float sAx, qAx, Gx;
    if (i == 0) {
        sAx = g_sA[b * 128 + jm1]; qAx = g_qA[b * 128 + jm1];
        Gx = g_G[(b * 128 + jm1) * 128 + jm1];
    } else {
        sAx = g_sA[b * 128 + i - 1]; qAx = g_qA[b * 128 + i - 1];
        Gx = g_G[(b * 128 + i - 1) * 128 + jm1];
    }
    float mu = (sAx + sBj) * invD;
    float var = fmaxf((qAx + qBj + 2.f * Gx) * invD - mu * mu, 0.f);
    float rsc = rsqrtf(var + 1e-5f);
    float c0 = -mu * rsc;
    ull rs2 = pk(rsc, rsc), c02 = pk(c0, c0);

    const ull* BmT = g_BmT + b * 16384 + jm1;
    ull acc2[8];
    #pragma unroll
    for (int h = 0; h < 8; h++) acc2[h] = 0ULL;

    if (i == 0) {
        const ull* AT = g_AT + b * 16384 + jm1;
        #pragma unroll 4
        for (int d2 = 0; d2 < 128; d2++) {
            ull b2 = BmT[d2 * 128];
            ull a2 = AT[d2 * 128];
            ulonglong2 lp = ((const ulonglong2*)sL)[d2];
            const ulonglong2* up = (const ulonglong2*)(sU + d2 * 8);
            ulonglong2 u01 = up[0], u23 = up[1], u45 = up[2], u67 = up[3];
            ull x2 = add2(a2, b2);
            ull tz = fma2(x2, rs2, c02);
            ull y = relu2(fma2(tz, lp.x, lp.y));
            acc2[0] = fma2(y, u01.x, acc2[0]); acc2[1] = fma2(y, u01.y, acc2[1]);
            acc2[2] = fma2(y, u23.x, acc2[2]); acc2[3] = fma2(y, u23.y, acc2[3]);
            acc2[4] = fma2(y, u45.x, acc2[4]); acc2[5] = fma2(y, u45.y, acc2[5]);
            acc2[6] = fma2(y, u67.x, acc2[6]); acc2[7] = fma2(y, u67.y, acc2[7]);
        }
    } else {
        const ull* aRow = sA2 + s * 128;
        #pragma unroll 4
        for (int d2 = 0; d2 < 128; d2++) {
            ull b2 = BmT[d2 * 128];
            ull a2 = aRow[d2];
            ulonglong2 lp = ((const ulonglong2*)sL)[d2];
            const ulonglong2* up = (const ulonglong2*)(sU + d2 * 8);
            ulonglong2 u01 = up[0], u23 = up[1], u45 = up[2], u67 = up[3];
            ull x2 = add2(a2, b2);
            ull tz = fma2(x2, rs2, c02);
            ull y = relu2(fma2(tz, lp.x, lp.y));
            acc2[0] = fma2(y, u01.x, acc2[0]); acc2[1] = fma2(y, u01.y, acc2[1]);
            acc2[2] = fma2(y, u23.x, acc2[2]); acc2[3] = fma2(y, u23.y, acc2[3]);
            acc2[4] = fma2(y, u45.x, acc2[4]); acc2[5] = fma2(y, u45.y, acc2[5]);
            acc2[6] = fma2(y, u67.x, acc2[6]); acc2[7] = fma2(y, u67.y, acc2[7]);
        }
    }

    #pragma unroll
    for (int h = 0; h < 8; h++) {
        float lo, hi; upk(acc2[h], lo, hi);
        g_E[((size_t)(b * 8 + h) * 129 + i) * 128 + jm1] = lo + hi;
    }
}

// ---------------------------------------------------------------------------
// k_softmax: block per (b,i), warp per head. Prior log-odds computed inline.
__global__ void __launch_bounds__(256) k_softmax(const float* __restrict__ prior,
                                                 float* __restrict__ out_attn) {
    int blk = blockIdx.x;
    int b = blk / 129, i = blk % 129;
    int w = threadIdx.x >> 5, lane = threadIdx.x & 31;
    int h = w;
    int bh = b * 8 + h;
    float qv = g_qa[bh * 129 + i];
    const float* Erow = g_E + (size_t)(bh * 129 + i) * 128;
    const float* kap = g_ka + bh * 129;
    const float* pr = prior + ((size_t)bh * 128 + (i - 1)) * 128;

    float lg[5];
    float mx = -3.4e38f;
    #pragma unroll
    for (int m = 0; m < 5; m++) {
        int j = lane + 32 * m;
        float L = -3.4e38f;
        if (j <= 128) {
            bool ok = (j >= 1) && (i == 0 || j != i);
            if (!ok) L = -1e9f;
            else {
                L = Erow[j - 1] + qv + kap[j];
                if (i >= 1) {
                    float p = pr[j - 1];
                    p = fminf(fmaxf(p, 1e-6f), 1.f - 1e-6f);
                    L += __logf(p) - __logf(1.f - p);
                }
            }
        }
        lg[m] = L;
        mx = fmaxf(mx, L);
    }
    #pragma unroll
    for (int off = 16; off; off >>= 1)
        mx = fmaxf(mx, __shfl_xor_sync(0xffffffffu, mx, off));
    float sum = 0.f;
    #pragma unroll
    for (int m = 0; m < 5; m++) {
        int j = lane + 32 * m;
        if (j <= 128) { lg[m] = __expf(lg[m] - mx); sum += lg[m]; }
        else lg[m] = 0.f;
    }
    #pragma unroll
    for (int off = 16; off; off >>= 1)
        sum += __shfl_xor_sync(0xffffffffu, sum, off);
    float inv = 1.f / sum;
    float* ao = out_attn + ((size_t)bh * 129 + i) * TT;
    #pragma unroll
    for (int m = 0; m < 5; m++) {
        int j = lane + 32 * m;
        if (j <= 128) ao[j] = lg[m] * inv;
    }
}

// ---------------------------------------------------------------------------
__global__ void __launch_bounds__(256) k_ctx(const float* __restrict__ attn,
                                             float* __restrict__ out_basis) {
    int t = blockIdx.x;
    int b = t >> 5, h = (t >> 2) & 7, iq = t & 3;
    int i0q = iq * 32;
    int iend = (iq == 3) ? 129 : (i0q + 32);
    int tid = threadIdx.x, w = tid >> 5, lane = tid & 31;

    __shared__ __align__(16) float vsh[TT * 33];
    __shared__ __align__(16) float a_sh[8 * 132];

    for (int idx = tid; idx < TT * 32; idx += 256) {
        int j = idx >> 5, d = idx & 31;
        vsh[j * 33 + d] = g_V[((size_t)b * TT + j) * DD + h * HDIM + d];
    }
    __syncthreads();

    for (int i0 = i0q; i0 < iend; i0 += 8) {
        int rows = iend - i0; if (rows > 8) rows = 8;
        if (w < rows) {
            int i = i0 + w;
            const float* ar = attn + ((size_t)(b * HH + h) * TT + i) * TT;
            #pragma unroll
            for (int m = 0; m < 4; m++)
                a_sh[w * 132 + lane + 32 * m] = ar[lane + 32 * m];
            if (lane == 0) a_sh[w * 132 + 128] = ar[128];
        }
        __syncthreads();
        if (w < rows) {
            int i = i0 + w;
            const float4* arow = (const float4*)(a_sh + w * 132);
            float acc = 0.f;
            #pragma unroll 8
            for (int jj = 0; jj < 32; jj++) {
                float4 av = arow[jj];
                int jb = jj * 4;
                acc = fmaf(av.x, vsh[(jb + 0) * 33 + lane], acc);
                acc = fmaf(av.y, vsh[(jb + 1) * 33 + lane], acc);
                acc = fmaf(av.z, vsh[(jb + 2) * 33 + lane], acc);
                acc = fmaf(av.w, vsh[(jb + 3) * 33 + lane], acc);
            }
            acc = fmaf(a_sh[w * 132 + 128], vsh[128 * 33 + lane], acc);
            out_basis[(((size_t)b * TT + i) * HH + h) * HDIM + lane] = acc;
        }
        __syncthreads();
    }
}

// ---------------------------------------------------------------------------
extern "C" void kernel_launch(void* const* d_in, const int* in_sizes, int n_in,
                              void* d_out, int out_size) {
    const float* desc  = (const float*)d_in[0];
    const float* nv    = (const float*)d_in[1];
    const float* prior = (const float*)d_in[2];
    const float* Wq    = (const float*)d_in[3];
    const float* bq    = (const float*)d_in[4];
    const float* Wk    = (const float*)d_in[5];
    const float* bk    = (const float*)d_in[6];
    const float* Wv    = (const float*)d_in[7];
    const float* bv    = (const float*)d_in[8];
    const float* wa    = (const float*)d_in[9];
    const float* ba    = (const float*)d_in[10];
    const float* We1   = (const float*)d_in[11];
    const float* be1   = (const float*)d_in[12];
    const float* lng   = (const float*)d_in[13];
    const float* lnb   = (const float*)d_in[14];
    const float* We2   = (const float*)d_in[15];
    const float* be2   = (const float*)d_in[16];

    float* out      = (float*)d_out;
    float* out_attn = out + (size_t)BB * TT * HH * HDIM;

    k_setup<<<25, 256>>>(Wq, Wk, We2, wa, bq, bk, be2);
    k_fused<<<325, 256>>>(desc, nv, We1, be1, Wv, bv, ba);
    k_stats<<<321, 256>>>(lng, lnb);
    k_edge<<<BB * 65, 256>>>();
    k_softmax<<<BB * 129, 256>>>(prior, out_attn);
    k_ctx<<<BB * HH * 4, 256>>>(out_attn, out);
}

// round 14
// speedup vs baseline: 1.5917x; 1.5917x over previous
#include <cuda_runtime.h>
#include <math.h>

#define BB 8
#define SS 128
#define DD 256
#define HH 8
#define TT 129
#define HDIM 32

typedef unsigned long long ull;

// Scratch (no allocations allowed)
__device__ __align__(16) float g_A [BB*SS*DD];   // desc @ We1[:256] + be1
__device__ __align__(16) float g_Bm[BB*SS*DD];   // desc @ We1[256:]
__device__ __align__(16) float g_V [BB*TT*DD];   // nv @ Wv + bv
__device__ __align__(16) float g_u [DD*HH];      // We2 folded with wa_e
__device__ __align__(16) float g_wq[DD*HH];
__device__ __align__(16) float g_wk[DD*HH];
__device__ float g_qa[BB*HH*TT];                 // includes bq_eff + ba + be2_eff
__device__ float g_ka[BB*HH*TT];                 // includes bk_eff
__device__ float g_beff[3*HH];
__device__ float g_bias[BB*HH*SS*SS];            // log-odds prior bias
__device__ float g_sA[BB*SS];
__device__ float g_qA[BB*SS];
__device__ float g_sB[BB*SS];
__device__ float g_qB[BB*SS];
__device__ __align__(16) float g_G [BB*SS*SS];   // Gram: dot(A'_i, Bm_j)
__device__ __align__(16) ull g_BmT[BB*128*128];  // [b][d2][j]
__device__ __align__(16) ull g_AT [BB*128*128];  // same for A'
__device__ __align__(16) ull g_u2 [128*8];       // [d2][h]
__device__ __align__(16) ull g_lnp[128*2];       // [d2]{gamma2, beta2}
__device__ float g_E[BB*HH*129*128];             // raw head scores

// ---- f32x2 helpers -------------------------------------------------------
__device__ __forceinline__ ull pk(float a, float b) {
    ull r; asm("mov.b64 %0,{%1,%2};" : "=l"(r) : "f"(a), "f"(b)); return r;
}
__device__ __forceinline__ void upk(ull v, float& a, float& b) {
    asm("mov.b64 {%0,%1},%2;" : "=f"(a), "=f"(b) : "l"(v));
}
__device__ __forceinline__ ull add2(ull a, ull b) {
    ull r; asm("add.rn.f32x2 %0,%1,%2;" : "=l"(r) : "l"(a), "l"(b)); return r;
}
__device__ __forceinline__ ull mul2(ull a, ull b) {
    ull r; asm("mul.rn.f32x2 %0,%1,%2;" : "=l"(r) : "l"(a), "l"(b)); return r;
}
__device__ __forceinline__ ull fma2(ull a, ull b, ull c) {
    ull r; asm("fma.rn.f32x2 %0,%1,%2,%3;" : "=l"(r) : "l"(a), "l"(b), "l"(c)); return r;
}
__device__ __forceinline__ ull relu2(ull v) {
    ull a; asm("and.b64 %0,%1,0x7FFFFFFF7FFFFFFF;" : "=l"(a) : "l"(v));
    const ull HALF2 = 0x3F0000003F000000ULL;
    return mul2(add2(v, a), HALF2);
}

// ---------------------------------------------------------------------------
__global__ void __launch_bounds__(256) k_setup(
        const float* __restrict__ Wq, const float* __restrict__ Wk,
        const float* __restrict__ We2, const float* __restrict__ wa,
        const float* __restrict__ bq, const float* __restrict__ bk,
        const float* __restrict__ be2) {
    int blk = blockIdx.x;
    if (blk < 24) {
        int which = blk >> 3, h = blk & 7;
        const float* W = (which == 0) ? Wq : (which == 1) ? Wk : We2;
        float* dst = (which == 0) ? g_wq : (which == 1) ? g_wk : g_u;
        __shared__ float was[32];
        if (threadIdx.x < 32) was[threadIdx.x] = wa[which * 32 + threadIdx.x];
        __syncthreads();
        int d = threadIdx.x;
        const float4* wp = (const float4*)(W + d * 256 + h * 32);
        float s = 0.f;
        #pragma unroll
        for (int e4 = 0; e4 < 8; e4++) {
            float4 v = wp[e4];
            s = fmaf(v.x, was[e4*4+0], s);
            s = fmaf(v.y, was[e4*4+1], s);
            s = fmaf(v.z, was[e4*4+2], s);
            s = fmaf(v.w, was[e4*4+3], s);
        }
        dst[d * 8 + h] = s;
    } else {
        __shared__ float was[96];
        if (threadIdx.x < 96) was[threadIdx.x] = wa[threadIdx.x];
        __syncthreads();
        int d = threadIdx.x;
        if (d < 24) {
            int h = d & 7, which = d >> 3;
            const float* bp = (which == 0) ? bq : (which == 1) ? bk : be2;
            int wo = which * 32;
            float s = 0.f;
            for (int e = 0; e < 32; e++) s += bp[h * 32 + e] * was[wo + e];
            g_beff[d] = s;
        }
    }
}

// ---------------------------------------------------------------------------
__device__ __forceinline__ void gemm_tile64(const float* __restrict__ X,
                                            const float* __restrict__ W,
                                            const float* __restrict__ bias,
                                            int M, int wRowOff, int bm, int bn,
                                            float* __restrict__ C,
                                            float* XsT, float* Ws) {
    int tid = threadIdx.x;
    int xr = tid >> 2, xc = (tid & 3) * 4;
    int wk = tid >> 4, wn = (tid & 15) * 4;
    int tr = (tid >> 4) * 4, tc = (tid & 15) * 4;
    float acc[4][4];
    #pragma unroll
    for (int r = 0; r < 4; r++)
        #pragma unroll
        for (int c = 0; c < 4; c++) acc[r][c] = 0.f;

    int gr = bm + xr;
    float4 xv, wv;
    if (gr < M) xv = *(const float4*)&X[gr * 256 + xc];
    else xv = make_float4(0.f, 0.f, 0.f, 0.f);
    wv = *(const float4*)&W[(wRowOff + wk) * 256 + bn + wn];

    #pragma unroll 1
    for (int p = 0; p < 16; p++) {
        XsT[(xc + 0) * 68 + xr] = xv.x;
        XsT[(xc + 1) * 68 + xr] = xv.y;
        XsT[(xc + 2) * 68 + xr] = xv.z;
        XsT[(xc + 3) * 68 + xr] = xv.w;
        *(float4*)&Ws[wk * 68 + wn] = wv;
        __syncthreads();
        if (p < 15) {
            int k0 = (p + 1) * 16;
            if (gr < M) xv = *(const float4*)&X[gr * 256 + k0 + xc];
            wv = *(const float4*)&W[(wRowOff + k0 + wk) * 256 + bn + wn];
        }
        #pragma unroll
        for (int kk = 0; kk < 16; kk++) {
            float4 a = *(const float4*)&XsT[kk * 68 + tr];
            float4 b = *(const float4*)&Ws[kk * 68 + tc];
            acc[0][0] = fmaf(a.x, b.x, acc[0][0]); acc[0][1] = fmaf(a.x, b.y, acc[0][1]);
            acc[0][2] = fmaf(a.x, b.z, acc[0][2]); acc[0][3] = fmaf(a.x, b.w, acc[0][3]);
            acc[1][0] = fmaf(a.y, b.x, acc[1][0]); acc[1][1] = fmaf(a.y, b.y, acc[1][1]);
            acc[1][2] = fmaf(a.y, b.z, acc[1][2]); acc[1][3] = fmaf(a.y, b.w, acc[1][3]);
            acc[2][0] = fmaf(a.z, b.x, acc[2][0]); acc[2][1] = fmaf(a.z, b.y, acc[2][1]);
            acc[2][2] = fmaf(a.z, b.z, acc[2][2]); acc[2][3] = fmaf(a.z, b.w, acc[2][3]);
            acc[3][0] = fmaf(a.w, b.x, acc[3][0]); acc[3][1] = fmaf(a.w, b.y, acc[3][1]);
            acc[3][2] = fmaf(a.w, b.z, acc[3][2]); acc[3][3] = fmaf(a.w, b.w, acc[3][3]);
        }
        __syncthreads();
    }
    #pragma unroll
    for (int r = 0; r < 4; r++) {
        int gr2 = bm + tr + r;
        if (gr2 < M) {
            float4 v = make_float4(acc[r][0], acc[r][1], acc[r][2], acc[r][3]);
            if (bias) {
                v.x += bias[bn + tc + 0]; v.y += bias[bn + tc + 1];
                v.z += bias[bn + tc + 2]; v.w += bias[bn + tc + 3];
            }
            *(float4*)&C[gr2 * 256 + bn + tc] = v;
        }
    }
}

__global__ void __launch_bounds__(256) k_fused(const float* __restrict__ desc,
                                               const float* __restrict__ nv,
                                               const float* __restrict__ prior,
                                               const float* __restrict__ We1,
                                               const float* __restrict__ be1,
                                               const float* __restrict__ Wv,
                                               const float* __restrict__ bv,
                                               const float* __restrict__ ba) {
    __shared__ __align__(16) float XsT[16 * 68];
    __shared__ __align__(16) float Ws[16 * 68];
    int t = blockIdx.x;
    int tid = threadIdx.x;
    if (t < 128) {
        int mt = t & 15, nt = t >> 4;
        bool isB = nt >= 4;
        gemm_tile64(desc, We1, isB ? (const float*)0 : be1, BB * SS,
                    isB ? 256 : 0, mt * 64, (nt & 3) * 64,
                    isB ? g_Bm : g_A, XsT, Ws);
    } else if (t < 196) {
        int t2 = t - 128;
        int mt = t2 % 17, nt = t2 / 17;
        gemm_tile64(nv, Wv, bv, BB * TT, 0, mt * 64, nt * 64, g_V, XsT, Ws);
    } else if (t < 325) {
        int w = tid >> 5, lane = tid & 31;
        int row = (t - 196) * 8 + w;
        int b = row / TT, tt = row % TT;
        float accq[8], acck[8];
        #pragma unroll
        for (int h = 0; h < 8; h++) { accq[h] = 0.f; acck[h] = 0.f; }
        #pragma unroll
        for (int k = 0; k < 8; k++) {
            int d = lane + 32 * k;
            float xv = nv[row * DD + d];
            #pragma unroll
            for (int h = 0; h < 8; h++) {
                accq[h] = fmaf(xv, g_wq[d * 8 + h], accq[h]);
                acck[h] = fmaf(xv, g_wk[d * 8 + h], acck[h]);
            }
        }
        #pragma unroll
        for (int h = 0; h < 8; h++) {
            #pragma unroll
            for (int off = 16; off; off >>= 1) {
                accq[h] += __shfl_xor_sync(0xffffffffu, accq[h], off);
                acck[h] += __shfl_xor_sync(0xffffffffu, acck[h], off);
            }
        }
        if (lane == 0) {
            float bav = ba[0];
            #pragma unroll
            for (int h = 0; h < 8; h++) {
                g_qa[(b * HH + h) * TT + tt] = accq[h] + g_beff[h] + bav + g_beff[16 + h];
                g_ka[(b * HH + h) * TT + tt] = acck[h] + g_beff[8 + h];
            }
        }
    } else {
        const int N = BB * HH * SS * SS;
        int base = (t - 325) * 256 + tid;
        for (int idx = base; idx < N; idx += 128 * 256) {
            float p = prior[idx];
            p = fminf(fmaxf(p, 1e-6f), 1.f - 1e-6f);
            g_bias[idx] = __logf(p) - __logf(1.f - p);
        }
    }
}

// ---------------------------------------------------------------------------
// k_stats: 0..31 Gram, 32..63 row stats, 64..319 transposes, 320 const packing
__global__ void __launch_bounds__(256) k_stats(const float* __restrict__ lng,
                                               const float* __restrict__ lnb) {
    int t = blockIdx.x, tid = threadIdx.x;
    if (t < 32) {
        __shared__ __align__(16) float As[16 * 68];
        __shared__ __align__(16) float Bs[16 * 68];
        int b = t >> 2, q = t & 3;
        int ti = (q >> 1) * 64, tj = (q & 1) * 64;
        int xr = tid >> 2, xc = (tid & 3) * 4;
        int tr = (tid >> 4) * 4, tc = (tid & 15) * 4;
        float acc[4][4];
        #pragma unroll
        for (int r = 0; r < 4; r++)
            #pragma unroll
            for (int c = 0; c < 4; c++) acc[r][c] = 0.f;

        const float* Abase = g_A + (b * 128 + ti) * 256;
        const float* Bbase = g_Bm + (b * 128 + tj) * 256;
        float4 av = *(const float4*)&Abase[xr * 256 + xc];
        float4 bv = *(const float4*)&Bbase[xr * 256 + xc];
        #pragma unroll 1
        for (int p = 0; p < 16; p++) {
            As[(xc + 0) * 68 + xr] = av.x; As[(xc + 1) * 68 + xr] = av.y;
            As[(xc + 2) * 68 + xr] = av.z; As[(xc + 3) * 68 + xr] = av.w;
            Bs[(xc + 0) * 68 + xr] = bv.x; Bs[(xc + 1) * 68 + xr] = bv.y;
            Bs[(xc + 2) * 68 + xr] = bv.z; Bs[(xc + 3) * 68 + xr] = bv.w;
            __syncthreads();
            if (p < 15) {
                int k0 = (p + 1) * 16;
                av = *(const float4*)&Abase[xr * 256 + k0 + xc];
                bv = *(const float4*)&Bbase[xr * 256 + k0 + xc];
            }
            #pragma unroll
            for (int kk = 0; kk < 16; kk++) {
                float4 a = *(const float4*)&As[kk * 68 + tr];
                float4 b2 = *(const float4*)&Bs[kk * 68 + tc];
                acc[0][0] = fmaf(a.x, b2.x, acc[0][0]); acc[0][1] = fmaf(a.x, b2.y, acc[0][1]);
                acc[0][2] = fmaf(a.x, b2.z, acc[0][2]); acc[0][3] = fmaf(a.x, b2.w, acc[0][3]);
                acc[1][0] = fmaf(a.y, b2.x, acc[1][0]); acc[1][1] = fmaf(a.y, b2.y, acc[1][1]);
                acc[1][2] = fmaf(a.y, b2.z, acc[1][2]); acc[1][3] = fmaf(a.y, b2.w, acc[1][3]);
                acc[2][0] = fmaf(a.z, b2.x, acc[2][0]); acc[2][1] = fmaf(a.z, b2.y, acc[2][1]);
                acc[2][2] = fmaf(a.z, b2.z, acc[2][2]); acc[2][3] = fmaf(a.z, b2.w, acc[2][3]);
                acc[3][0] = fmaf(a.w, b2.x, acc[3][0]); acc[3][1] = fmaf(a.w, b2.y, acc[3][1]);
                acc[3][2] = fmaf(a.w, b2.z, acc[3][2]); acc[3][3] = fmaf(a.w, b2.w, acc[3][3]);
            }
            __syncthreads();
        }
        #pragma unroll
        for (int r = 0; r < 4; r++) {
            float4 v = make_float4(acc[r][0], acc[r][1], acc[r][2], acc[r][3]);
            *(float4*)&g_G[(b * 128 + ti + tr + r) * 128 + tj + tc] = v;
        }
    } else if (t < 64) {
        int w = tid >> 5, lane = tid & 31;
        int r0 = (t - 32) * 64;
        for (int it = 0; it < 8; it++) {
            int row = r0 + w * 8 + it;
            const float* src = (row < 1024) ? (g_A + row * 256) : (g_Bm + (row - 1024) * 256);
            const float4* sp = (const float4*)(src + lane * 8);
            float4 v0 = sp[0], v1 = sp[1];
            float s = v0.x + v0.y + v0.z + v0.w + v1.x + v1.y + v1.z + v1.w;
            float q = v0.x*v0.x + v0.y*v0.y + v0.z*v0.z + v0.w*v0.w
                    + v1.x*v1.x + v1.y*v1.y + v1.z*v1.z + v1.w*v1.w;
            #pragma unroll
            for (int off = 16; off; off >>= 1) {
                s += __shfl_xor_sync(0xffffffffu, s, off);
                q += __shfl_xor_sync(0xffffffffu, q, off);
            }
            if (lane == 0) {
                if (row < 1024) { g_sA[row] = s; g_qA[row] = q; }
                else            { g_sB[row - 1024] = s; g_qB[row - 1024] = q; }
            }
        }
    } else if (t < 320) {
        __shared__ ull ts[32][33];
        int tb = t - 64;
        int b = tb >> 5, m = (tb >> 4) & 1, tile = tb & 15;
        int td = tile >> 2, tj = tile & 3;
        const float* src = m ? g_Bm : g_A;
        ull* dst = m ? g_BmT : g_AT;
        int ty = tid >> 5, tx = tid & 31;
        #pragma unroll
        for (int r = 0; r < 4; r++) {
            int jloc = ty + 8 * r;
            int j = tj * 32 + jloc;
            int d2 = td * 32 + tx;
            float2 v = *(const float2*)&src[(b * 128 + j) * 256 + 2 * d2];
            ts[jloc][tx] = pk(v.x, v.y);
        }
        __syncthreads();
        #pragma unroll
        for (int r = 0; r < 4; r++) {
            int d2loc = ty + 8 * r;
            int d2 = td * 32 + d2loc;
            int j = tj * 32 + tx;
            dst[b * 16384 + d2 * 128 + j] = ts[tx][d2loc];
        }
    } else {
        for (int idx = tid; idx < 1024; idx += 256) {
            int d2 = idx >> 3, h = idx & 7;
            g_u2[idx] = pk(g_u[(2 * d2) * 8 + h], g_u[(2 * d2 + 1) * 8 + h]);
        }
        if (tid < 128) {
            g_lnp[2 * tid]     = pk(lng[2 * tid], lng[2 * tid + 1]);
            g_lnp[2 * tid + 1] = pk(lnb[2 * tid], lnb[2 * tid + 1]);
        }
    }
}

// ---------------------------------------------------------------------------
// k_edge v3.1: 128 thr, tid = j-1, i-tile of 2; interleaved a-pair LDS.128;
// deep unroll for LDG MLP.
__global__ void __launch_bounds__(128) k_edge() {
    int blk = blockIdx.x;
    int b = blk / 65, ib = blk % 65;
    int i0 = ib * 2;
    int tid = threadIdx.x;
    int jm1 = tid;                      // j-1 in 0..127

    __shared__ __align__(16) ull sU[1024];        // [d2][h]
    __shared__ __align__(16) ull sL[256];         // [d2]{g,b}
    __shared__ __align__(16) ulonglong2 sA2[128]; // [d2]{row i0-1, row i0}

    for (int idx = tid; idx < 1024; idx += 128) sU[idx] = g_u2[idx];
    sL[tid] = g_lnp[tid];
    sL[tid + 128] = g_lnp[tid + 128];
    {
        ulonglong2 v;
        v.x = (i0 >= 1)  ? ((const ull*)(g_A + (b * 128 + i0 - 1) * 256))[tid] : 0ULL;
        v.y = (i0 < 128) ? ((const ull*)(g_A + (b * 128 + i0) * 256))[tid]     : 0ULL;
        sA2[tid] = v;
    }
    __syncthreads();

    const float invD = 1.f / 256.f;
    float sBj = g_sB[b * 128 + jm1], qBj = g_qB[b * 128 + jm1];
    int nvalid = (i0 + 1 <= 128) ? 2 : 1;

    ull rs2[2], c02[2];
    #pragma unroll
    for (int s = 0; s < 2; s++) {
        if (s >= nvalid) break;
        int i = i0 + s;
        float sAx, qAx, Gx;
        if (i == 0) {
            sAx = g_sA[b * 128 + jm1]; qAx = g_qA[b * 128 + jm1];
            Gx = g_G[(b * 128 + jm1) * 128 + jm1];
        } else {
            sAx = g_sA[b * 128 + i - 1]; qAx = g_qA[b * 128 + i - 1];
            Gx = g_G[(b * 128 + i - 1) * 128 + jm1];
        }
        float mu = (sAx + sBj) * invD;
        float var = fmaxf((qAx + qBj + 2.f * Gx) * invD - mu * mu, 0.f);
        float rs = rsqrtf(var + 1e-5f);
        float c0 = -mu * rs;
        rs2[s] = pk(rs, rs); c02[s] = pk(c0, c0);
    }

    const ull* BmT = g_BmT + b * 16384 + jm1;
    ull acc2[2][8];
    #pragma unroll
    for (int s = 0; s < 2; s++)
        #pragma unroll
        for (int h = 0; h < 8; h++) acc2[s][h] = 0ULL;

    if (i0 == 0) {
        // s=0 is cls (i=0): a from AT (lane-varying); s=1 uses sA2[d2].y
        const ull* AT = g_AT + b * 16384 + jm1;
        #pragma unroll 8
        for (int d2 = 0; d2 < 128; d2++) {
            ull b2 = BmT[d2 * 128];
            ulonglong2 lp = ((const ulonglong2*)sL)[d2];
            const ulonglong2* up = (const ulonglong2*)(sU + d2 * 8);
            ulonglong2 u01 = up[0], u23 = up[1], u45 = up[2], u67 = up[3];
            ulonglong2 a12 = sA2[d2];
            {
                ull a2 = AT[d2 * 128];
                ull x2 = add2(a2, b2);
                ull tz = fma2(x2, rs2[0], c02[0]);
                ull y = relu2(fma2(tz, lp.x, lp.y));
                acc2[0][0] = fma2(y, u01.x, acc2[0][0]); acc2[0][1] = fma2(y, u01.y, acc2[0][1]);
                acc2[0][2] = fma2(y, u23.x, acc2[0][2]); acc2[0][3] = fma2(y, u23.y, acc2[0][3]);
                acc2[0][4] = fma2(y, u45.x, acc2[0][4]); acc2[0][5] = fma2(y, u45.y, acc2[0][5]);
                acc2[0][6] = fma2(y, u67.x, acc2[0][6]); acc2[0][7] = fma2(y, u67.y, acc2[0][7]);
            }
            {
                ull x2 = add2(a12.y, b2);
                ull tz = fma2(x2, rs2[1], c02[1]);
                ull y = relu2(fma2(tz, lp.x, lp.y));
                acc2[1][0] = fma2(y, u01.x, acc2[1][0]); acc2[1][1] = fma2(y, u01.y, acc2[1][1]);
                acc2[1][2] = fma2(y, u23.x, acc2[1][2]); acc2[1][3] = fma2(y, u23.y, acc2[1][3]);
                acc2[1][4] = fma2(y, u45.x, acc2[1][4]); acc2[1][5] = fma2(y, u45.y, acc2[1][5]);
                acc2[1][6] = fma2(y, u67.x, acc2[1][6]); acc2[1][7] = fma2(y, u67.y, acc2[1][7]);
            }
        }
    } else if (nvalid == 2) {
        #pragma unroll 8
        for (int d2 = 0; d2 < 128; d2++) {
            ull b2 = BmT[d2 * 128];
            ulonglong2 lp = ((const ulonglong2*)sL)[d2];
            const ulonglong2* up = (const ulonglong2*)(sU + d2 * 8);
            ulonglong2 u01 = up[0], u23 = up[1], u45 = up[2], u67 = up[3];
            ulonglong2 a12 = sA2[d2];
            {
                ull x2 = add2(a12.x, b2);
                ull tz = fma2(x2, rs2[0], c02[0]);
                ull y = relu2(fma2(tz, lp.x, lp.y));
                acc2[0][0] = fma2(y, u01.x, acc2[0][0]); acc2[0][1] = fma2(y, u01.y, acc2[0][1]);
                acc2[0][2] = fma2(y, u23.x, acc2[0][2]); acc2[0][3] = fma2(y, u23.y, acc2[0][3]);
                acc2[0][4] = fma2(y, u45.x, acc2[0][4]); acc2[0][5] = fma2(y, u45.y, acc2[0][5]);
                acc2[0][6] = fma2(y, u67.x, acc2[0][6]); acc2[0][7] = fma2(y, u67.y, acc2[0][7]);
            }
            {
                ull x2 = add2(a12.y, b2);
                ull tz = fma2(x2, rs2[1], c02[1]);
                ull y = relu2(fma2(tz, lp.x, lp.y));
                acc2[1][0] = fma2(y, u01.x, acc2[1][0]); acc2[1][1] = fma2(y, u01.y, acc2[1][1]);
                acc2[1][2] = fma2(y, u23.x, acc2[1][2]); acc2[1][3] = fma2(y, u23.y, acc2[1][3]);
                acc2[1][4] = fma2(y, u45.x, acc2[1][4]); acc2[1][5] = fma2(y, u45.y, acc2[1][5]);
                acc2[1][6] = fma2(y, u67.x, acc2[1][6]); acc2[1][7] = fma2(y, u67.y, acc2[1][7]);
            }
        }
    } else {
        #pragma unroll 8
        for (int d2 = 0; d2 < 128; d2++) {
            ull b2 = BmT[d2 * 128];
            ulonglong2 lp = ((const ulonglong2*)sL)[d2];
            const ulonglong2* up = (const ulonglong2*)(sU + d2 * 8);
            ulonglong2 u01 = up[0], u23 = up[1], u45 = up[2], u67 = up[3];
            ulonglong2 a12 = sA2[d2];
            ull x2 = add2(a12.x, b2);
            ull tz = fma2(x2, rs2[0], c02[0]);
            ull y = relu2(fma2(tz, lp.x, lp.y));
            acc2[0][0] = fma2(y, u01.x, acc2[0][0]); acc2[0][1] = fma2(y, u01.y, acc2[0][1]);
            acc2[0][2] = fma2(y, u23.x, acc2[0][2]); acc2[0][3] = fma2(y, u23.y, acc2[0][3]);
            acc2[0][4] = fma2(y, u45.x, acc2[0][4]); acc2[0][5] = fma2(y, u45.y, acc2[0][5]);
            acc2[0][6] = fma2(y, u67.x, acc2[0][6]); acc2[0][7] = fma2(y, u67.y, acc2[0][7]);
        }
    }

    #pragma unroll
    for (int s = 0; s < 2; s++) {
        if (s >= nvalid) break;
        int i = i0 + s;
        #pragma unroll
        for (int h = 0; h < 8; h++) {
            float lo, hi; upk(acc2[s][h], lo, hi);
            g_E[((size_t)(b * 8 + h) * 129 + i) * 128 + jm1] = lo + hi;
        }
    }
}

// ---------------------------------------------------------------------------
// k_softmax: block per (b,i), warp per head. (R10 version: reads g_bias.)
__global__ void __launch_bounds__(256) k_softmax(float* __restrict__ out_attn) {
    int blk = blockIdx.x;
    int b = blk / 129, i = blk % 129;
    int w = threadIdx.x >> 5, lane = threadIdx.x & 31;
    int h = w;
    int bh = b * 8 + h;
    float qv = g_qa[bh * 129 + i];
    const float* Erow = g_E + (size_t)(bh * 129 + i) * 128;
    const float* kap = g_ka + bh * 129;
    const float* bi = g_bias + ((size_t)bh * 128 + (i - 1)) * 128;

    float lg[5];
    float mx = -3.4e38f;
    #pragma unroll
    for (int m = 0; m < 5; m++) {
        int j = lane + 32 * m;
        float L = -3.4e38f;
        if (j <= 128) {
            bool ok = (j >= 1) && (i == 0 || j != i);
            if (!ok) L = -1e9f;
            else {
                L = Erow[j - 1] + qv + kap[j];
                if (i >= 1) L += bi[j - 1];
            }
        }
        lg[m] = L;
        mx = fmaxf(mx, L);
    }
    #pragma unroll
    for (int off = 16; off; off >>= 1)
        mx = fmaxf(mx, __shfl_xor_sync(0xffffffffu, mx, off));
    float sum = 0.f;
    #pragma unroll
    for (int m = 0; m < 5; m++) {
        int j = lane + 32 * m;
        if (j <= 128) { lg[m] = __expf(lg[m] - mx); sum += lg[m]; }
        else lg[m] = 0.f;
    }
    #pragma unroll
    for (int off = 16; off; off >>= 1)
        sum += __shfl_xor_sync(0xffffffffu, sum, off);
    float inv = 1.f / sum;
    float* ao = out_attn + ((size_t)bh * 129 + i) * TT;
    #pragma unroll
    for (int m = 0; m < 5; m++) {
        int j = lane + 32 * m;
        if (j <= 128) ao[j] = lg[m] * inv;
    }
}

// ---------------------------------------------------------------------------
__global__ void __launch_bounds__(256) k_ctx(const float* __restrict__ attn,
                                             float* __restrict__ out_basis) {
    int t = blockIdx.x;
    int b = t >> 5, h = (t >> 2) & 7, iq = t & 3;
    int i0q = iq * 32;
    int iend = (iq == 3) ? 129 : (i0q + 32);
    int tid = threadIdx.x, w = tid >> 5, lane = tid & 31;

    __shared__ __align__(16) float vsh[TT * 33];
    __shared__ __align__(16) float a_sh[8 * 132];

    for (int idx = tid; idx < TT * 32; idx += 256) {
        int j = idx >> 5, d = idx & 31;
        vsh[j * 33 + d] = g_V[((size_t)b * TT + j) * DD + h * HDIM + d];
    }
    __syncthreads();

    for (int i0 = i0q; i0 < iend; i0 += 8) {
        int rows = iend - i0; if (rows > 8) rows = 8;
        if (w < rows) {
            int i = i0 + w;
            const float* ar = attn + ((size_t)(b * HH + h) * TT + i) * TT;
            #pragma unroll
            for (int m = 0; m < 4; m++)
                a_sh[w * 132 + lane + 32 * m] = ar[lane + 32 * m];
            if (lane == 0) a_sh[w * 132 + 128] = ar[128];
        }
        __syncthreads();
        if (w < rows) {
            int i = i0 + w;
            const float4* arow = (const float4*)(a_sh + w * 132);
            float acc = 0.f;
            #pragma unroll 8
            for (int jj = 0; jj < 32; jj++) {
                float4 av = arow[jj];
                int jb = jj * 4;
                acc = fmaf(av.x, vsh[(jb + 0) * 33 + lane], acc);
                acc = fmaf(av.y, vsh[(jb + 1) * 33 + lane], acc);
                acc = fmaf(av.z, vsh[(jb + 2) * 33 + lane], acc);
                acc = fmaf(av.w, vsh[(jb + 3) * 33 + lane], acc);
            }
            acc = fmaf(a_sh[w * 132 + 128], vsh[128 * 33 + lane], acc);
            out_basis[(((size_t)b * TT + i) * HH + h) * HDIM + lane] = acc;
        }
        __syncthreads();
    }
}

// ---------------------------------------------------------------------------
extern "C" void kernel_launch(void* const* d_in, const int* in_sizes, int n_in,
                              void* d_out, int out_size) {
    const float* desc  = (const float*)d_in[0];
    const float* nv    = (const float*)d_in[1];
    const float* prior = (const float*)d_in[2];
    const float* Wq    = (const float*)d_in[3];
    const float* bq    = (const float*)d_in[4];
    const float* Wk    = (const float*)d_in[5];
    const float* bk    = (const float*)d_in[6];
    const float* Wv    = (const float*)d_in[7];
    const float* bv    = (const float*)d_in[8];
    const float* wa    = (const float*)d_in[9];
    const float* ba    = (const float*)d_in[10];
    const float* We1   = (const float*)d_in[11];
    const float* be1   = (const float*)d_in[12];
    const float* lng   = (const float*)d_in[13];
    const float* lnb   = (const float*)d_in[14];
    const float* We2   = (const float*)d_in[15];
    const float* be2   = (const float*)d_in[16];

    float* out      = (float*)d_out;
    float* out_attn = out + (size_t)BB * TT * HH * HDIM;

    k_setup<<<25, 256>>>(Wq, Wk, We2, wa, bq, bk, be2);
    k_fused<<<453, 256>>>(desc, nv, prior, We1, be1, Wv, bv, ba);
    k_stats<<<321, 256>>>(lng, lnb);
    k_edge<<<BB * 65, 128>>>();
    k_softmax<<<BB * 129, 256>>>(out_attn);
    k_ctx<<<BB * HH * 4, 256>>>(out_attn, out);
}